// round 1
// baseline (speedup 1.0000x reference)
#include <cuda_runtime.h>
#include <math.h>

#define TPB 256
#define B 8
#define C1 256
#define HW1 4096
#define C2 512
#define HW2 1024

// ---------------- scratch (device globals; no allocation allowed) ----------
__device__ float g_Gs_s1[B * HW1];
__device__ float g_Gs_t1[B * HW1];
__device__ float g_Gc_s1[B * C1];
__device__ float g_Gc_t1[B * C1];
__device__ float g_Gs_s2[B * HW2];
__device__ float g_Gs_t2[B * HW2];
__device__ float g_Gc_s2[B * C2];
__device__ float g_Gc_t2[B * C2];

__device__ float g_Ms1[B * HW1];
__device__ float g_Mc1[B * C1];
__device__ float g_Ms2[B * HW2];
__device__ float g_Mc2[B * C2];

__device__ double g_lat;
__device__ double g_slam1;
__device__ double g_slam2;

// ---------------- block reduce helpers --------------------------------------
__device__ __forceinline__ float blockReduceSum(float v) {
    __shared__ float sh[32];
    int lane = threadIdx.x & 31, warp = threadIdx.x >> 5;
    int nw = blockDim.x >> 5;
#pragma unroll
    for (int o = 16; o > 0; o >>= 1) v += __shfl_down_sync(0xffffffffu, v, o);
    __syncthreads();  // protect sh reuse across calls
    if (lane == 0) sh[warp] = v;
    __syncthreads();
    if (threadIdx.x == 0) {
        float r = 0.f;
        for (int w = 0; w < nw; w++) r += sh[w];
        sh[0] = r;
    }
    __syncthreads();
    return sh[0];
}

__device__ __forceinline__ float blockReduceMax(float v) {
    __shared__ float sh[32];
    int lane = threadIdx.x & 31, warp = threadIdx.x >> 5;
    int nw = blockDim.x >> 5;
#pragma unroll
    for (int o = 16; o > 0; o >>= 1) v = fmaxf(v, __shfl_down_sync(0xffffffffu, v, o));
    __syncthreads();
    if (lane == 0) sh[warp] = v;
    __syncthreads();
    if (threadIdx.x == 0) {
        float r = sh[0];
        for (int w = 1; w < nw; w++) r = fmaxf(r, sh[w]);
        sh[0] = r;
    }
    __syncthreads();
    return sh[0];
}

// ---------------- init: zero accumulators every launch ----------------------
__global__ void init_kernel() {
    int i = blockIdx.x * blockDim.x + threadIdx.x;
    int stride = gridDim.x * blockDim.x;
    for (int k = i; k < B * HW1; k += stride) { g_Gs_s1[k] = 0.f; g_Gs_t1[k] = 0.f; }
    for (int k = i; k < B * HW2; k += stride) { g_Gs_s2[k] = 0.f; g_Gs_t2[k] = 0.f; }
    for (int k = i; k < B * C1; k += stride)  { g_Gc_s1[k] = 0.f; g_Gc_t1[k] = 0.f; }
    for (int k = i; k < B * C2; k += stride)  { g_Gc_s2[k] = 0.f; g_Gc_t2[k] = 0.f; }
    if (i == 0) { g_lat = 0.0; g_slam1 = 0.0; g_slam2 = 0.0; }
}

// ---------------- pass 1: attention map sums (one full read of s,t) ---------
// grid: B * (C/CCHUNK) * (HW/HWCHUNK); each block owns a (b, c-chunk, hw-chunk)
// Spatial sums accumulate in per-thread registers (exclusive hw slots),
// channel sums via per-channel block reduce. Atomics only at combine points.
template <int LEVEL, int Cc, int HWc, int CCHUNK, int HWCHUNK>
__global__ void pass1_kernel(const float* __restrict__ s, const float* __restrict__ t) {
    float* Gs_s = (LEVEL == 1) ? g_Gs_s1 : g_Gs_s2;
    float* Gs_t = (LEVEL == 1) ? g_Gs_t1 : g_Gs_t2;
    float* Gc_s = (LEVEL == 1) ? g_Gc_s1 : g_Gc_s2;
    float* Gc_t = (LEVEL == 1) ? g_Gc_t1 : g_Gc_t2;

    constexpr int NC = Cc / CCHUNK;
    constexpr int NH = HWc / HWCHUNK;
    constexpr int PER = HWCHUNK / TPB;

    int blk = blockIdx.x;
    int b = blk / (NC * NH);
    int r = blk % (NC * NH);
    int cc = r / NH;
    int hh = r % NH;
    int tid = threadIdx.x;
    int lane = tid & 31, warp = tid >> 5;

    float gs_s[PER], gs_t[PER];
#pragma unroll
    for (int k = 0; k < PER; k++) { gs_s[k] = 0.f; gs_t[k] = 0.f; }

    __shared__ float red[2 * (TPB / 32)];
    const int hwbase = hh * HWCHUNK;

    for (int ci = 0; ci < CCHUNK; ci++) {
        int c = cc * CCHUNK + ci;
        const float* ps = s + ((size_t)b * Cc + c) * HWc + hwbase;
        const float* pt = t + ((size_t)b * Cc + c) * HWc + hwbase;
        float part_s = 0.f, part_t = 0.f;
#pragma unroll
        for (int k = 0; k < PER; k++) {
            float vs = fabsf(ps[tid + k * TPB]);
            float vt = fabsf(pt[tid + k * TPB]);
            part_s += vs; part_t += vt;
            gs_s[k] += vs; gs_t[k] += vt;
        }
#pragma unroll
        for (int o = 16; o > 0; o >>= 1) {
            part_s += __shfl_down_sync(0xffffffffu, part_s, o);
            part_t += __shfl_down_sync(0xffffffffu, part_t, o);
        }
        if (lane == 0) { red[warp] = part_s; red[warp + TPB / 32] = part_t; }
        __syncthreads();
        if (tid == 0) {
            float as = 0.f, at = 0.f;
#pragma unroll
            for (int w = 0; w < TPB / 32; w++) { as += red[w]; at += red[w + TPB / 32]; }
            atomicAdd(&Gc_s[b * Cc + c], as);
            atomicAdd(&Gc_t[b * Cc + c], at);
        }
        __syncthreads();
    }
#pragma unroll
    for (int k = 0; k < PER; k++) {
        atomicAdd(&Gs_s[b * HWc + hwbase + tid + k * TPB], gs_s[k]);
        atomicAdd(&Gs_t[b * HWc + hwbase + tid + k * TPB], gs_t[k]);
    }
}

// ---------------- softmax + lat (tiny: B blocks) -----------------------------
// Note: stored sums are raw (not /C or /HW). Gs = S/C, Gc = S/HW:
//   z_spatial = (Ss+St)/(C*T) = (Ss+St)*2/C ;  lat_spatial = sum (Ss-St)^2 / C^2
//   z_channel = (Cs+Ct)*2/HW               ;  lat_channel = sum (Cs-Ct)^2 / HW^2
template <int LEVEL, int Cc, int HWc>
__global__ void softmax_lat_kernel() {
    const float* Gs_s = (LEVEL == 1) ? g_Gs_s1 : g_Gs_s2;
    const float* Gs_t = (LEVEL == 1) ? g_Gs_t1 : g_Gs_t2;
    const float* Gc_s = (LEVEL == 1) ? g_Gc_s1 : g_Gc_s2;
    const float* Gc_t = (LEVEL == 1) ? g_Gc_t1 : g_Gc_t2;
    float* Ms = (LEVEL == 1) ? g_Ms1 : g_Ms2;
    float* Mc = (LEVEL == 1) ? g_Mc1 : g_Mc2;

    __shared__ float zbuf[HWc];  // HWc >= Cc for both levels
    int b = blockIdx.x;
    int tid = threadIdx.x;

    // ---- spatial ----
    float latp = 0.f, mx = -INFINITY;
    for (int i = tid; i < HWc; i += TPB) {
        float ss = Gs_s[b * HWc + i], st = Gs_t[b * HWc + i];
        float d = ss - st;
        latp += d * d;
        float z = (ss + st) * (2.0f / (float)Cc);
        zbuf[i] = z;
        mx = fmaxf(mx, z);
    }
    float m = blockReduceMax(mx);
    float se = 0.f;
    for (int i = tid; i < HWc; i += TPB) {
        float e = expf(zbuf[i] - m);
        zbuf[i] = e;
        se += e;
    }
    float S = blockReduceSum(se);
    float sc = (float)HWc / S;
    for (int i = tid; i < HWc; i += TPB) Ms[b * HWc + i] = zbuf[i] * sc;
    float lat_s = blockReduceSum(latp);  // also syncs before zbuf reuse

    // ---- channel ----
    float latc = 0.f, mxc = -INFINITY;
    for (int i = tid; i < Cc; i += TPB) {
        float cs = Gc_s[b * Cc + i], ct = Gc_t[b * Cc + i];
        float d = cs - ct;
        latc += d * d;
        float z = (cs + ct) * (2.0f / (float)HWc);
        zbuf[i] = z;
        mxc = fmaxf(mxc, z);
    }
    float mc2 = blockReduceMax(mxc);
    float sec = 0.f;
    for (int i = tid; i < Cc; i += TPB) {
        float e = expf(zbuf[i] - mc2);
        zbuf[i] = e;
        sec += e;
    }
    float Sc = blockReduceSum(sec);
    float scc = (float)Cc / Sc;
    for (int i = tid; i < Cc; i += TPB) Mc[b * Cc + i] = zbuf[i] * scc;
    float lat_c = blockReduceSum(latc);

    if (tid == 0) {
        double contrib = (double)lat_s / ((double)Cc * (double)Cc) +
                         (double)lat_c / ((double)HWc * (double)HWc);
        atomicAdd(&g_lat, contrib);
    }
}

// ---------------- pass 2: slam (second full read of s,t) --------------------
template <int LEVEL, int Cc, int HWc>
__global__ void pass2_kernel(const float* __restrict__ s, const float* __restrict__ t) {
    const float* Ms = (LEVEL == 1) ? g_Ms1 : g_Ms2;
    const float* Mc = (LEVEL == 1) ? g_Mc1 : g_Mc2;
    double* slam = (LEVEL == 1) ? &g_slam1 : &g_slam2;

    constexpr long long CHW = (long long)Cc * HWc;
    constexpr long long N4 = (long long)B * CHW / 4;
    long long gid = (long long)blockIdx.x * blockDim.x + threadIdx.x;
    long long stride = (long long)gridDim.x * blockDim.x;
    const float4* s4 = (const float4*)s;
    const float4* t4 = (const float4*)t;

    float acc = 0.f;
    for (long long i = gid; i < N4; i += stride) {
        float4 a = s4[i];
        float4 bb = t4[i];
        long long e = i * 4;
        int b = (int)(e / CHW);
        int rem = (int)(e - (long long)b * CHW);
        int c = rem / HWc;        // HWc is power of two -> shift
        int hw = rem & (HWc - 1);
        float mc = Mc[b * Cc + c];
        float4 ms = *(const float4*)&Ms[b * HWc + hw];
        float d0 = a.x - bb.x, d1 = a.y - bb.y, d2 = a.z - bb.z, d3 = a.w - bb.w;
        acc += (d0 * d0 * ms.x + d1 * d1 * ms.y + d2 * d2 * ms.z + d3 * d3 * ms.w) * mc;
    }
    float bl = blockReduceSum(acc);
    if (threadIdx.x == 0) atomicAdd(slam, (double)bl);
}

// ---------------- final scalar combine --------------------------------------
__global__ void final_kernel(float* out, int out_size) {
    double lam = sqrt(g_slam1) + sqrt(g_slam2);
    double att = (4e-4 * g_lat + 2e-2 * lam) / (double)B / 2.0;  // ATT=1, 2 levels
    out[0] = (float)(att * (double)B);
    if (out_size > 1) out[1] = (float)att;
}

// ---------------- launch ------------------------------------------------------
extern "C" void kernel_launch(void* const* d_in, const int* in_sizes, int n_in,
                              void* d_out, int out_size) {
    const float* stu1 = (const float*)d_in[1];
    const float* tea1 = (const float*)d_in[2];
    const float* stu2 = (const float*)d_in[3];
    const float* tea2 = (const float*)d_in[4];
    float* out = (float*)d_out;

    init_kernel<<<96, TPB>>>();

    // level1: 8 * (256/32) * (4096/1024) = 256 blocks
    pass1_kernel<1, C1, HW1, 32, 1024><<<B * (C1 / 32) * (HW1 / 1024), TPB>>>(stu1, tea1);
    // level2: 8 * (512/16) * (1024/1024) = 256 blocks
    pass1_kernel<2, C2, HW2, 16, 1024><<<B * (C2 / 16) * (HW2 / 1024), TPB>>>(stu2, tea2);

    softmax_lat_kernel<1, C1, HW1><<<B, TPB>>>();
    softmax_lat_kernel<2, C2, HW2><<<B, TPB>>>();

    pass2_kernel<1, C1, HW1><<<1184, TPB>>>(stu1, tea1);
    pass2_kernel<2, C2, HW2><<<1184, TPB>>>(stu2, tea2);

    final_kernel<<<1, 1>>>(out, out_size);
}

// round 2
// speedup vs baseline: 1.4706x; 1.4706x over previous
#include <cuda_runtime.h>
#include <math.h>

#define B   8
#define C1  256
#define HW1 4096
#define C2  512
#define HW2 1024

#define TPB  256
#define STPB 512

#define CCH  16                 // channels per tile
#define HWCH 1024               // hw elements per tile (256 thr * float4)
#define NC1  (C1 / CCH)         // 16
#define NH1  (HW1 / HWCH)       // 4
#define NC2  (C2 / CCH)         // 32
#define NH2  (HW2 / HWCH)       // 1
#define TILES1 (B * NC1 * NH1)  // 512
#define TILES2 (B * NC2 * NH2)  // 256

#define P2B1 1024
#define P2B2 512

// ---------------- scratch (direct-write partials; no init kernel needed) ----
__device__ float g_Gs1p[2][NC1][B * HW1];        // raw |x| channel-sums, partial per c-chunk
__device__ float g_Gs2p[2][NC2][B * HW2];
__device__ float g_Gc1p[2][B * C1][NH1 * 8];     // raw |x| spatial-sums, partial per (hh,warp)
__device__ float g_Gc2p[2][B * C2][NH2 * 8];

__device__ float g_Ms1[B * HW1];
__device__ float g_Mc1[B * C1];
__device__ float g_Ms2[B * HW2];
__device__ float g_Mc2[B * C2];

__device__ double g_latpart[16];                 // one slot per softmax block
__device__ float  g_p2[P2B1 + P2B2];             // per-block slam partials

// ---------------- reduce helpers --------------------------------------------
__device__ __forceinline__ float blockReduceSum(float v) {
    __shared__ float sh[32];
    int lane = threadIdx.x & 31, warp = threadIdx.x >> 5;
    int nw = blockDim.x >> 5;
#pragma unroll
    for (int o = 16; o > 0; o >>= 1) v += __shfl_down_sync(0xffffffffu, v, o);
    __syncthreads();
    if (lane == 0) sh[warp] = v;
    __syncthreads();
    if (threadIdx.x == 0) {
        float r = 0.f;
        for (int w = 0; w < nw; w++) r += sh[w];
        sh[0] = r;
    }
    __syncthreads();
    return sh[0];
}

__device__ __forceinline__ float blockReduceMax(float v) {
    __shared__ float sh[32];
    int lane = threadIdx.x & 31, warp = threadIdx.x >> 5;
    int nw = blockDim.x >> 5;
#pragma unroll
    for (int o = 16; o > 0; o >>= 1) v = fmaxf(v, __shfl_down_sync(0xffffffffu, v, o));
    __syncthreads();
    if (lane == 0) sh[warp] = v;
    __syncthreads();
    if (threadIdx.x == 0) {
        float r = sh[0];
        for (int w = 1; w < nw; w++) r = fmaxf(r, sh[w]);
        sh[0] = r;
    }
    __syncthreads();
    return sh[0];
}

// ---------------- pass 1: one full read, direct-write partials ---------------
union F2D { float2 f2; double d; };

template <int Cc, int HWc, int NC, int NH>
__device__ __forceinline__ void pass1_tile(
    const float* __restrict__ s, const float* __restrict__ t,
    float* __restrict__ Gsp_s, float* __restrict__ Gsp_t,   // [NC][B*HWc]
    float* __restrict__ Gcp_s, float* __restrict__ Gcp_t,   // [B*Cc][NH*8]
    int tile)
{
    const int tid = threadIdx.x;
    const int lane = tid & 31, warp = tid >> 5;
    const int b  = tile / (NC * NH);
    const int r  = tile % (NC * NH);
    const int cc = r / NH;
    const int hh = r % NH;
    const int hwbase = hh * HWCH;
    const int c0 = cc * CCH;

    const float4* ps = (const float4*)(s + ((size_t)b * Cc + c0) * HWc + hwbase) + tid;
    const float4* pt = (const float4*)(t + ((size_t)b * Cc + c0) * HWc + hwbase) + tid;
    constexpr int STR4 = HWc / 4;

    float4 as = make_float4(0.f, 0.f, 0.f, 0.f);
    float4 at = make_float4(0.f, 0.f, 0.f, 0.f);

#pragma unroll
    for (int ci = 0; ci < CCH; ci++) {
        float4 vs = ps[(size_t)ci * STR4];
        float4 vt = pt[(size_t)ci * STR4];
        vs.x = fabsf(vs.x); vs.y = fabsf(vs.y); vs.z = fabsf(vs.z); vs.w = fabsf(vs.w);
        vt.x = fabsf(vt.x); vt.y = fabsf(vt.y); vt.z = fabsf(vt.z); vt.w = fabsf(vt.w);
        as.x += vs.x; as.y += vs.y; as.z += vs.z; as.w += vs.w;
        at.x += vt.x; at.y += vt.y; at.z += vt.z; at.w += vt.w;

        // per-warp channel partial (packed 2 floats in one 64-bit shfl chain)
        F2D u;
        u.f2 = make_float2((vs.x + vs.y) + (vs.z + vs.w),
                           (vt.x + vt.y) + (vt.z + vt.w));
#pragma unroll
        for (int o = 16; o > 0; o >>= 1) {
            F2D v; v.d = __shfl_down_sync(0xffffffffu, u.d, o);
            u.f2.x += v.f2.x; u.f2.y += v.f2.y;
        }
        if (lane == 0) {
            int idx = (b * Cc + c0 + ci) * (NH * 8) + hh * 8 + warp;
            Gcp_s[idx] = u.f2.x;
            Gcp_t[idx] = u.f2.y;
        }
    }
    float4* os = (float4*)(Gsp_s + (size_t)cc * (B * HWc) + b * HWc + hwbase) + tid;
    float4* ot = (float4*)(Gsp_t + (size_t)cc * (B * HWc) + b * HWc + hwbase) + tid;
    *os = as;
    *ot = at;
}

__global__ void pass1_kernel(const float* __restrict__ s1, const float* __restrict__ t1,
                             const float* __restrict__ s2, const float* __restrict__ t2) {
    int bid = blockIdx.x;
    if (bid < TILES1)
        pass1_tile<C1, HW1, NC1, NH1>(s1, t1,
            &g_Gs1p[0][0][0], &g_Gs1p[1][0][0],
            &g_Gc1p[0][0][0], &g_Gc1p[1][0][0], bid);
    else
        pass1_tile<C2, HW2, NC2, NH2>(s2, t2,
            &g_Gs2p[0][0][0], &g_Gs2p[1][0][0],
            &g_Gc2p[0][0][0], &g_Gc2p[1][0][0], bid - TILES1);
}

// ---------------- softmax + lat (16 blocks, fused levels) --------------------
template <int Cc, int HWc, int NC, int NPART>
__device__ __forceinline__ void softmax_level(
    const float* __restrict__ Gsp_s, const float* __restrict__ Gsp_t,
    const float* __restrict__ Gcp_s, const float* __restrict__ Gcp_t,
    float* __restrict__ Ms, float* __restrict__ Mc,
    int b, float* zbuf, double* latout)
{
    const int tid = threadIdx.x;

    // ---- spatial ----
    float latp = 0.f, mx = -INFINITY;
    for (int i = tid; i < HWc; i += STPB) {
        float ss = 0.f, st = 0.f;
#pragma unroll
        for (int p = 0; p < NC; p++) {
            ss += Gsp_s[(size_t)p * (B * HWc) + b * HWc + i];
            st += Gsp_t[(size_t)p * (B * HWc) + b * HWc + i];
        }
        float d = ss - st;
        latp += d * d;
        float z = (ss + st) * (2.0f / (float)Cc);  // /C (mean) then /T (T=0.5)
        zbuf[i] = z;
        mx = fmaxf(mx, z);
    }
    float m = blockReduceMax(mx);
    float se = 0.f;
    for (int i = tid; i < HWc; i += STPB) {
        float e = __expf(zbuf[i] - m);
        zbuf[i] = e;
        se += e;
    }
    float S = blockReduceSum(se);
    float sc = (float)HWc / S;
    for (int i = tid; i < HWc; i += STPB) Ms[b * HWc + i] = zbuf[i] * sc;
    float lat_s = blockReduceSum(latp);   // barrier also fences zbuf reuse

    // ---- channel ----
    float latc = 0.f, mxc = -INFINITY;
    for (int i = tid; i < Cc; i += STPB) {
        float cs = 0.f, ct = 0.f;
#pragma unroll
        for (int k = 0; k < NPART; k++) {
            cs += Gcp_s[(size_t)(b * Cc + i) * NPART + k];
            ct += Gcp_t[(size_t)(b * Cc + i) * NPART + k];
        }
        float d = cs - ct;
        latc += d * d;
        float z = (cs + ct) * (2.0f / (float)HWc);
        zbuf[i] = z;
        mxc = fmaxf(mxc, z);
    }
    float m2 = blockReduceMax(mxc);
    float sec = 0.f;
    for (int i = tid; i < Cc; i += STPB) {
        float e = __expf(zbuf[i] - m2);
        zbuf[i] = e;
        sec += e;
    }
    float Sc = blockReduceSum(sec);
    float scc = (float)Cc / Sc;
    for (int i = tid; i < Cc; i += STPB) Mc[b * Cc + i] = zbuf[i] * scc;
    float lat_c = blockReduceSum(latc);

    if (tid == 0)
        *latout = (double)lat_s / ((double)Cc * (double)Cc) +
                  (double)lat_c / ((double)HWc * (double)HWc);
}

__global__ void softmax_kernel() {
    __shared__ float zbuf[HW1];   // 16 KB; HW1 >= HW2, C1, C2
    int bid = blockIdx.x;
    if (bid < B)
        softmax_level<C1, HW1, NC1, NH1 * 8>(
            &g_Gs1p[0][0][0], &g_Gs1p[1][0][0],
            &g_Gc1p[0][0][0], &g_Gc1p[1][0][0],
            g_Ms1, g_Mc1, bid, zbuf, &g_latpart[bid]);
    else
        softmax_level<C2, HW2, NC2, NH2 * 8>(
            &g_Gs2p[0][0][0], &g_Gs2p[1][0][0],
            &g_Gc2p[0][0][0], &g_Gc2p[1][0][0],
            g_Ms2, g_Mc2, bid - B, zbuf, &g_latpart[bid]);
}

// ---------------- pass 2: second full read, weighted SSE ---------------------
template <int Cc, int HWc, int LOGCHW, int LOGHW, int NBLK>
__device__ __forceinline__ float pass2_range(
    const float* __restrict__ s, const float* __restrict__ t,
    const float* __restrict__ Ms, const float* __restrict__ Mc, int bid)
{
    constexpr long long N4 = (long long)B * Cc * HWc / 4;
    constexpr long long STRIDE = (long long)NBLK * TPB;
    const float4* s4 = (const float4*)s;
    const float4* t4 = (const float4*)t;
    long long gid = (long long)bid * TPB + threadIdx.x;

    float acc = 0.f;
#pragma unroll
    for (long long i = gid; i < N4; i += STRIDE) {
        float4 a  = s4[i];
        float4 bb = t4[i];
        long long e = i << 2;
        int b   = (int)(e >> LOGCHW);
        int rem = (int)(e & ((1LL << LOGCHW) - 1));
        int c   = rem >> LOGHW;
        int hw  = rem & (HWc - 1);
        float mc = Mc[b * Cc + c];
        float4 ms = *(const float4*)(Ms + b * HWc + hw);
        float d0 = a.x - bb.x, d1 = a.y - bb.y, d2 = a.z - bb.z, d3 = a.w - bb.w;
        acc += (d0 * d0 * ms.x + d1 * d1 * ms.y + d2 * d2 * ms.z + d3 * d3 * ms.w) * mc;
    }
    return acc;
}

__global__ void pass2_kernel(const float* __restrict__ s1, const float* __restrict__ t1,
                             const float* __restrict__ s2, const float* __restrict__ t2) {
    float acc;
    if (blockIdx.x < P2B1)
        acc = pass2_range<C1, HW1, 20, 12, P2B1>(s1, t1, g_Ms1, g_Mc1, blockIdx.x);
    else
        acc = pass2_range<C2, HW2, 19, 10, P2B2>(s2, t2, g_Ms2, g_Mc2, blockIdx.x - P2B1);
    float bl = blockReduceSum(acc);
    if (threadIdx.x == 0) g_p2[blockIdx.x] = bl;
}

// ---------------- final combine ----------------------------------------------
__global__ void final_kernel(float* out, int out_size) {
    int tid = threadIdx.x;
    double a1 = 0.0, a2 = 0.0;
    for (int i = tid; i < P2B1; i += TPB) a1 += (double)g_p2[i];
    for (int i = P2B1 + tid; i < P2B1 + P2B2; i += TPB) a2 += (double)g_p2[i];

    __shared__ double sh1[32], sh2[32];
    int lane = tid & 31, warp = tid >> 5;
#pragma unroll
    for (int o = 16; o > 0; o >>= 1) {
        a1 += __shfl_down_sync(0xffffffffu, a1, o);
        a2 += __shfl_down_sync(0xffffffffu, a2, o);
    }
    if (lane == 0) { sh1[warp] = a1; sh2[warp] = a2; }
    __syncthreads();
    if (tid == 0) {
        double s1 = 0.0, s2 = 0.0;
        for (int w = 0; w < TPB / 32; w++) { s1 += sh1[w]; s2 += sh2[w]; }
        double lat = 0.0;
        for (int i = 0; i < 16; i++) lat += g_latpart[i];
        double lam = sqrt(s1) + sqrt(s2);
        double att = (4e-4 * lat + 2e-2 * lam) / (double)B / 2.0;  // ATT=1, /BS, /2 levels
        out[0] = (float)(att * (double)B);
        if (out_size > 1) out[1] = (float)att;
    }
}

// ---------------- launch ------------------------------------------------------
extern "C" void kernel_launch(void* const* d_in, const int* in_sizes, int n_in,
                              void* d_out, int out_size) {
    const float* stu1 = (const float*)d_in[1];
    const float* tea1 = (const float*)d_in[2];
    const float* stu2 = (const float*)d_in[3];
    const float* tea2 = (const float*)d_in[4];
    float* out = (float*)d_out;

    pass1_kernel<<<TILES1 + TILES2, TPB>>>(stu1, tea1, stu2, tea2);
    softmax_kernel<<<16, STPB>>>();
    pass2_kernel<<<P2B1 + P2B2, TPB>>>(stu1, tea1, stu2, tea2);
    final_kernel<<<1, TPB>>>(out, out_size);
}

// round 3
// speedup vs baseline: 1.5237x; 1.0361x over previous
#include <cuda_runtime.h>
#include <cuda_fp16.h>
#include <math.h>

#define B   8
#define C1  256
#define HW1 4096
#define C2  512
#define HW2 1024

#define TPB  256
#define STPB 1024

#define CCH  16                 // channels per tile
#define HWCH 1024               // hw elements per tile (256 thr * float4)
#define NC1  (C1 / CCH)         // 16
#define NH1  (HW1 / HWCH)       // 4
#define NC2  (C2 / CCH)         // 32
#define NH2  (HW2 / HWCH)       // 1
#define TILES1 (B * NC1 * NH1)  // 512
#define TILES2 (B * NC2 * NH2)  // 256

#define P2B1 512
#define P2B2 256
#define P2TOT (P2B1 + P2B2)

// ---------------- scratch (device globals; no runtime allocation) -----------
__device__ float g_Gs1p[2][NC1][B * HW1];        // raw |x| channel-sum partials
__device__ float g_Gs2p[2][NC2][B * HW2];
__device__ float g_Gc1p[2][B * C1][NH1 * 8];     // raw |x| spatial-sum partials
__device__ float g_Gc2p[2][B * C2][NH2 * 8];

__device__ __half g_d1[B * C1 * HW1];            // fp16 stash of (s-t), level 1
__device__ __half g_d2[B * C2 * HW2];            // level 2

__device__ float g_Ms1[B * HW1];
__device__ float g_Mc1[B * C1];
__device__ float g_Ms2[B * HW2];
__device__ float g_Mc2[B * C2];

__device__ double g_latpart[16];
__device__ float  g_p2[P2TOT];
__device__ unsigned g_count = 0;

// ---------------- reduce helpers --------------------------------------------
__device__ __forceinline__ float blockReduceSum(float v) {
    __shared__ float sh[32];
    int lane = threadIdx.x & 31, warp = threadIdx.x >> 5;
    int nw = blockDim.x >> 5;
#pragma unroll
    for (int o = 16; o > 0; o >>= 1) v += __shfl_down_sync(0xffffffffu, v, o);
    __syncthreads();
    if (lane == 0) sh[warp] = v;
    __syncthreads();
    if (threadIdx.x == 0) {
        float r = 0.f;
        for (int w = 0; w < nw; w++) r += sh[w];
        sh[0] = r;
    }
    __syncthreads();
    return sh[0];
}

__device__ __forceinline__ float blockReduceMax(float v) {
    __shared__ float sh[32];
    int lane = threadIdx.x & 31, warp = threadIdx.x >> 5;
    int nw = blockDim.x >> 5;
#pragma unroll
    for (int o = 16; o > 0; o >>= 1) v = fmaxf(v, __shfl_down_sync(0xffffffffu, v, o));
    __syncthreads();
    if (lane == 0) sh[warp] = v;
    __syncthreads();
    if (threadIdx.x == 0) {
        float r = sh[0];
        for (int w = 1; w < nw; w++) r = fmaxf(r, sh[w]);
        sh[0] = r;
    }
    __syncthreads();
    return sh[0];
}

// ---------------- pass 1: one full read; partials + fp16 diff stash ----------
union F2D { float2 f2; double d; };

template <int Cc, int HWc, int NC, int NH>
__device__ __forceinline__ void pass1_tile(
    const float* __restrict__ s, const float* __restrict__ t,
    __half* __restrict__ dst,
    float* __restrict__ Gsp_s, float* __restrict__ Gsp_t,   // [NC][B*HWc]
    float* __restrict__ Gcp_s, float* __restrict__ Gcp_t,   // [B*Cc][NH*8]
    int tile)
{
    const int tid = threadIdx.x;
    const int lane = tid & 31, warp = tid >> 5;
    const int b  = tile / (NC * NH);
    const int r  = tile % (NC * NH);
    const int cc = r / NH;
    const int hh = r % NH;
    const int hwbase = hh * HWCH;
    const int c0 = cc * CCH;

    const size_t base4 = (((size_t)b * Cc + c0) * HWc + hwbase) / 4;
    const float4* ps = (const float4*)s + base4 + tid;
    const float4* pt = (const float4*)t + base4 + tid;
    uint2* pd = (uint2*)dst + base4 + tid;   // 4 halves per slot
    constexpr int STR4 = HWc / 4;

    float4 as = make_float4(0.f, 0.f, 0.f, 0.f);
    float4 at = make_float4(0.f, 0.f, 0.f, 0.f);

#pragma unroll
    for (int ci = 0; ci < CCH; ci++) {
        float4 vs = __ldcs(&ps[(size_t)ci * STR4]);   // evict-first: don't pollute L2
        float4 vt = __ldcs(&pt[(size_t)ci * STR4]);

        // diff stash (before abs)
        __half2 h01 = __floats2half2_rn(vs.x - vt.x, vs.y - vt.y);
        __half2 h23 = __floats2half2_rn(vs.z - vt.z, vs.w - vt.w);
        uint2 u;
        u.x = *reinterpret_cast<const unsigned*>(&h01);
        u.y = *reinterpret_cast<const unsigned*>(&h23);
        pd[(size_t)ci * STR4] = u;

        vs.x = fabsf(vs.x); vs.y = fabsf(vs.y); vs.z = fabsf(vs.z); vs.w = fabsf(vs.w);
        vt.x = fabsf(vt.x); vt.y = fabsf(vt.y); vt.z = fabsf(vt.z); vt.w = fabsf(vt.w);
        as.x += vs.x; as.y += vs.y; as.z += vs.z; as.w += vs.w;
        at.x += vt.x; at.y += vt.y; at.z += vt.z; at.w += vt.w;

        F2D u2;
        u2.f2 = make_float2((vs.x + vs.y) + (vs.z + vs.w),
                            (vt.x + vt.y) + (vt.z + vt.w));
#pragma unroll
        for (int o = 16; o > 0; o >>= 1) {
            F2D v; v.d = __shfl_down_sync(0xffffffffu, u2.d, o);
            u2.f2.x += v.f2.x; u2.f2.y += v.f2.y;
        }
        if (lane == 0) {
            int idx = (b * Cc + c0 + ci) * (NH * 8) + hh * 8 + warp;
            Gcp_s[idx] = u2.f2.x;
            Gcp_t[idx] = u2.f2.y;
        }
    }
    float4* os = (float4*)(Gsp_s + (size_t)cc * (B * HWc) + b * HWc + hwbase) + tid;
    float4* ot = (float4*)(Gsp_t + (size_t)cc * (B * HWc) + b * HWc + hwbase) + tid;
    *os = as;
    *ot = at;
}

__global__ void pass1_kernel(const float* __restrict__ s1, const float* __restrict__ t1,
                             const float* __restrict__ s2, const float* __restrict__ t2) {
    int bid = blockIdx.x;
    if (bid < TILES1)
        pass1_tile<C1, HW1, NC1, NH1>(s1, t1, g_d1,
            &g_Gs1p[0][0][0], &g_Gs1p[1][0][0],
            &g_Gc1p[0][0][0], &g_Gc1p[1][0][0], bid);
    else
        pass1_tile<C2, HW2, NC2, NH2>(s2, t2, g_d2,
            &g_Gs2p[0][0][0], &g_Gs2p[1][0][0],
            &g_Gc2p[0][0][0], &g_Gc2p[1][0][0], bid - TILES1);
}

// ---------------- softmax + lat (16 blocks; partials are L2-resident) --------
template <int Cc, int HWc, int NC, int NPART>
__device__ __forceinline__ void softmax_level(
    const float* __restrict__ Gsp_s, const float* __restrict__ Gsp_t,
    const float* __restrict__ Gcp_s, const float* __restrict__ Gcp_t,
    float* __restrict__ Ms, float* __restrict__ Mc,
    int b, float* zbuf, double* latout)
{
    const int tid = threadIdx.x;

    // ---- spatial ----
    float latp = 0.f, mx = -INFINITY;
    for (int i = tid; i < HWc; i += STPB) {
        float ss = 0.f, st = 0.f;
#pragma unroll
        for (int p = 0; p < NC; p++) {
            ss += Gsp_s[(size_t)p * (B * HWc) + b * HWc + i];
            st += Gsp_t[(size_t)p * (B * HWc) + b * HWc + i];
        }
        float d = ss - st;
        latp += d * d;
        float z = (ss + st) * (2.0f / (float)Cc);  // /C then /T (T=0.5)
        zbuf[i] = z;
        mx = fmaxf(mx, z);
    }
    float m = blockReduceMax(mx);
    float se = 0.f;
    for (int i = tid; i < HWc; i += STPB) {
        float e = __expf(zbuf[i] - m);
        zbuf[i] = e;
        se += e;
    }
    float S = blockReduceSum(se);
    float sc = (float)HWc / S;
    for (int i = tid; i < HWc; i += STPB) Ms[b * HWc + i] = zbuf[i] * sc;
    float lat_s = blockReduceSum(latp);

    // ---- channel ----
    float latc = 0.f, mxc = -INFINITY;
    for (int i = tid; i < Cc; i += STPB) {
        float cs = 0.f, ct = 0.f;
#pragma unroll
        for (int k = 0; k < NPART; k++) {
            cs += Gcp_s[(size_t)(b * Cc + i) * NPART + k];
            ct += Gcp_t[(size_t)(b * Cc + i) * NPART + k];
        }
        float d = cs - ct;
        latc += d * d;
        float z = (cs + ct) * (2.0f / (float)HWc);
        zbuf[i] = z;
        mxc = fmaxf(mxc, z);
    }
    float m2 = blockReduceMax(mxc);
    float sec = 0.f;
    for (int i = tid; i < Cc; i += STPB) {
        float e = __expf(zbuf[i] - m2);
        zbuf[i] = e;
        sec += e;
    }
    float Sc = blockReduceSum(sec);
    float scc = (float)Cc / Sc;
    for (int i = tid; i < Cc; i += STPB) Mc[b * Cc + i] = zbuf[i] * scc;
    float lat_c = blockReduceSum(latc);

    if (tid == 0)
        *latout = (double)lat_s / ((double)Cc * (double)Cc) +
                  (double)lat_c / ((double)HWc * (double)HWc);
}

__global__ void softmax_kernel() {
    __shared__ float zbuf[HW1];   // 16 KB
    int bid = blockIdx.x;
    if (bid == 0 && threadIdx.x == 0) g_count = 0;   // reset last-block counter
    if (bid < B)
        softmax_level<C1, HW1, NC1, NH1 * 8>(
            &g_Gs1p[0][0][0], &g_Gs1p[1][0][0],
            &g_Gc1p[0][0][0], &g_Gc1p[1][0][0],
            g_Ms1, g_Mc1, bid, zbuf, &g_latpart[bid]);
    else
        softmax_level<C2, HW2, NC2, NH2 * 8>(
            &g_Gs2p[0][0][0], &g_Gs2p[1][0][0],
            &g_Gc2p[0][0][0], &g_Gc2p[1][0][0],
            g_Ms2, g_Mc2, bid - B, zbuf, &g_latpart[bid]);
}

// ---------------- pass 2: fp16 stash read (L2), weighted SSE, fused final ----
__device__ __forceinline__ void discard_l2(const void* p) {
    unsigned long long g;
    asm("cvta.to.global.u64 %0, %1;" : "=l"(g) : "l"(p));
    asm volatile("discard.global.L2 [%0], 128;" :: "l"(g) : "memory");
}

template <int Cc, int HWc, int LOGCHW, int LOGHW, int NBLK>
__device__ __forceinline__ float pass2_range(
    const __half* __restrict__ dsrc,
    const float* __restrict__ Ms, const float* __restrict__ Mc, int bid)
{
    constexpr long long N16 = (long long)B * Cc * HWc / 8;   // uint4 = 8 halves
    constexpr long long STRIDE = (long long)NBLK * TPB;
    const uint4* d16 = (const uint4*)dsrc;
    long long gid = (long long)bid * TPB + threadIdx.x;

    float acc = 0.f;
#pragma unroll
    for (long long i = gid; i < N16; i += STRIDE) {
        uint4 v = d16[i];
        long long e = i << 3;
        int b   = (int)(e >> LOGCHW);
        int rem = (int)(e & ((1LL << LOGCHW) - 1));
        int c   = rem >> LOGHW;
        int hw  = rem & (HWc - 1);
        float mc = Mc[b * Cc + c];
        const float* msp = Ms + b * HWc + hw;
        float4 m0 = *(const float4*)msp;
        float4 m1 = *(const float4*)(msp + 4);

        float2 f0 = __half22float2(*reinterpret_cast<const __half2*>(&v.x));
        float2 f1 = __half22float2(*reinterpret_cast<const __half2*>(&v.y));
        float2 f2 = __half22float2(*reinterpret_cast<const __half2*>(&v.z));
        float2 f3 = __half22float2(*reinterpret_cast<const __half2*>(&v.w));

        float w = f0.x * f0.x * m0.x + f0.y * f0.y * m0.y
                + f1.x * f1.x * m0.z + f1.y * f1.y * m0.w
                + f2.x * f2.x * m1.x + f2.y * f2.y * m1.y
                + f3.x * f3.x * m1.z + f3.y * f3.y * m1.w;
        acc += w * mc;
    }
    return acc;
}

template <int HWc, int Cc, int NBLK>
__device__ __forceinline__ void pass2_discard(const __half* dsrc, int bid) {
    constexpr long long N16 = (long long)B * Cc * HWc / 8;
    constexpr long long STRIDE = (long long)NBLK * TPB;
    const uint4* d16 = (const uint4*)dsrc;
    long long gid = (long long)bid * TPB + threadIdx.x;
    for (long long i = gid; i < N16; i += STRIDE)
        if ((i & 7) == 0) discard_l2(&d16[i]);   // 8 uint4 = 128B line
}

__global__ void pass2_kernel(float* out, int out_size) {
    int bid = blockIdx.x;
    float acc;
    if (bid < P2B1)
        acc = pass2_range<C1, HW1, 20, 12, P2B1>(g_d1, g_Ms1, g_Mc1, bid);
    else
        acc = pass2_range<C2, HW2, 19, 10, P2B2>(g_d2, g_Ms2, g_Mc2, bid - P2B1);
    float bl = blockReduceSum(acc);   // includes __syncthreads: loads complete

    // consumed stash lines never write back to DRAM
    if (bid < P2B1) pass2_discard<HW1, C1, P2B1>(g_d1, bid);
    else            pass2_discard<HW2, C2, P2B2>(g_d2, bid - P2B1);

    __shared__ bool isLast;
    if (threadIdx.x == 0) {
        g_p2[bid] = bl;
        __threadfence();
        unsigned old = atomicAdd(&g_count, 1u);
        isLast = (old == P2TOT - 1);
    }
    __syncthreads();
    if (!isLast) return;

    // ---- fused final combine (last block) ----
    __threadfence();
    int tid = threadIdx.x;
    double a1 = 0.0, a2 = 0.0;
    for (int i = tid; i < P2B1; i += TPB) a1 += (double)g_p2[i];
    for (int i = P2B1 + tid; i < P2TOT; i += TPB) a2 += (double)g_p2[i];

    __shared__ double sh1[32], sh2[32];
    int lane = tid & 31, warp = tid >> 5;
#pragma unroll
    for (int o = 16; o > 0; o >>= 1) {
        a1 += __shfl_down_sync(0xffffffffu, a1, o);
        a2 += __shfl_down_sync(0xffffffffu, a2, o);
    }
    if (lane == 0) { sh1[warp] = a1; sh2[warp] = a2; }
    __syncthreads();
    if (tid == 0) {
        double s1 = 0.0, s2 = 0.0;
        for (int w = 0; w < TPB / 32; w++) { s1 += sh1[w]; s2 += sh2[w]; }
        double lat = 0.0;
        for (int i = 0; i < 16; i++) lat += g_latpart[i];
        double lam = sqrt(s1) + sqrt(s2);
        double att = (4e-4 * lat + 2e-2 * lam) / (double)B / 2.0;  // ATT=1, /BS, /2 levels
        out[0] = (float)(att * (double)B);
        if (out_size > 1) out[1] = (float)att;
    }
}

// ---------------- launch ------------------------------------------------------
extern "C" void kernel_launch(void* const* d_in, const int* in_sizes, int n_in,
                              void* d_out, int out_size) {
    const float* stu1 = (const float*)d_in[1];
    const float* tea1 = (const float*)d_in[2];
    const float* stu2 = (const float*)d_in[3];
    const float* tea2 = (const float*)d_in[4];
    float* out = (float*)d_out;

    pass1_kernel<<<TILES1 + TILES2, TPB>>>(stu1, tea1, stu2, tea2);
    softmax_kernel<<<16, STPB>>>();
    pass2_kernel<<<P2TOT, TPB>>>(out, out_size);
}

// round 4
// speedup vs baseline: 1.9396x; 1.2730x over previous
#include <cuda_runtime.h>
#include <cuda_fp16.h>
#include <math.h>

#define B   8
#define C1  256
#define HW1 4096
#define C2  512
#define HW2 1024

#define TPB  256
#define STPB 1024

#define CCH  8                  // channels per tile (== warps per block)
#define HWCH 1024               // hw elements per tile (256 thr * float4)
#define NC1  (C1 / CCH)         // 32
#define NH1  (HW1 / HWCH)       // 4
#define NC2  (C2 / CCH)         // 64
#define NH2  (HW2 / HWCH)       // 1
#define TILES1 (B * NC1 * NH1)  // 1024
#define TILES2 (B * NC2 * NH2)  // 512

#define P2B1 512
#define P2B2 256
#define P2TOT (P2B1 + P2B2)

// ---------------- scratch (device globals; no runtime allocation) -----------
__device__ float g_Gs1p[2][NC1][B * HW1];        // raw |x| channel-sum partials
__device__ float g_Gs2p[2][NC2][B * HW2];
__device__ float g_Gc1p[2][B * C1][NH1];         // raw |x| spatial-sum partials
__device__ float g_Gc2p[2][B * C2][NH2];

__device__ __half g_d1[B * C1 * HW1];            // fp16 stash of (s-t), level 1
__device__ __half g_d2[B * C2 * HW2];            // level 2

__device__ float g_Ms1[B * HW1];
__device__ float g_Mc1[B * C1];
__device__ float g_Ms2[B * HW2];
__device__ float g_Mc2[B * C2];

__device__ double g_latpart[16];
__device__ float  g_p2[P2TOT];
__device__ unsigned g_count = 0;

union F2D { float2 f2; double d; };

// ---------------- reduce helpers --------------------------------------------
__device__ __forceinline__ float blockReduceSum(float v) {
    __shared__ float sh[32];
    int lane = threadIdx.x & 31, warp = threadIdx.x >> 5;
    int nw = blockDim.x >> 5;
#pragma unroll
    for (int o = 16; o > 0; o >>= 1) v += __shfl_down_sync(0xffffffffu, v, o);
    __syncthreads();
    if (lane == 0) sh[warp] = v;
    __syncthreads();
    if (threadIdx.x == 0) {
        float r = 0.f;
        for (int w = 0; w < nw; w++) r += sh[w];
        sh[0] = r;
    }
    __syncthreads();
    return sh[0];
}

__device__ __forceinline__ float blockReduceMax(float v) {
    __shared__ float sh[32];
    int lane = threadIdx.x & 31, warp = threadIdx.x >> 5;
    int nw = blockDim.x >> 5;
#pragma unroll
    for (int o = 16; o > 0; o >>= 1) v = fmaxf(v, __shfl_down_sync(0xffffffffu, v, o));
    __syncthreads();
    if (lane == 0) sh[warp] = v;
    __syncthreads();
    if (threadIdx.x == 0) {
        float r = sh[0];
        for (int w = 1; w < nw; w++) r = fmaxf(r, sh[w]);
        sh[0] = r;
    }
    __syncthreads();
    return sh[0];
}

// ---------------- pass 1: pure-load loop + smem-staged channel reduce --------
template <int Cc, int HWc, int NC, int NH>
__device__ __forceinline__ void pass1_tile(
    const float* __restrict__ s, const float* __restrict__ t,
    __half* __restrict__ dst,
    float* __restrict__ Gsp_s, float* __restrict__ Gsp_t,   // [NC][B*HWc]
    float* __restrict__ Gcp_s, float* __restrict__ Gcp_t,   // [B*Cc][NH]
    float2 (*stage)[TPB],
    int tile)
{
    const int tid = threadIdx.x;
    const int lane = tid & 31, warp = tid >> 5;
    const int b  = tile / (NC * NH);
    const int r  = tile % (NC * NH);
    const int cc = r / NH;
    const int hh = r % NH;
    const int hwbase = hh * HWCH;
    const int c0 = cc * CCH;

    const size_t base4 = (((size_t)b * Cc + c0) * HWc + hwbase) / 4;
    const float4* ps = (const float4*)s + base4 + tid;
    const float4* pt = (const float4*)t + base4 + tid;
    uint2* pd = (uint2*)dst + base4 + tid;   // 4 halves per slot
    constexpr int STR4 = HWc / 4;

    float4 as = make_float4(0.f, 0.f, 0.f, 0.f);
    float4 at = make_float4(0.f, 0.f, 0.f, 0.f);

    // pure streaming loop: no cross-lane dependencies
#pragma unroll
    for (int ci = 0; ci < CCH; ci++) {
        float4 vs = __ldcs(&ps[(size_t)ci * STR4]);   // evict-first
        float4 vt = __ldcs(&pt[(size_t)ci * STR4]);

        __half2 h01 = __floats2half2_rn(vs.x - vt.x, vs.y - vt.y);
        __half2 h23 = __floats2half2_rn(vs.z - vt.z, vs.w - vt.w);
        uint2 u;
        u.x = *reinterpret_cast<const unsigned*>(&h01);
        u.y = *reinterpret_cast<const unsigned*>(&h23);
        pd[(size_t)ci * STR4] = u;

        vs.x = fabsf(vs.x); vs.y = fabsf(vs.y); vs.z = fabsf(vs.z); vs.w = fabsf(vs.w);
        vt.x = fabsf(vt.x); vt.y = fabsf(vt.y); vt.z = fabsf(vt.z); vt.w = fabsf(vt.w);
        as.x += vs.x; as.y += vs.y; as.z += vs.z; as.w += vs.w;
        at.x += vt.x; at.y += vt.y; at.z += vt.z; at.w += vt.w;

        stage[ci][tid] = make_float2((vs.x + vs.y) + (vs.z + vs.w),
                                     (vt.x + vt.y) + (vt.z + vt.w));
    }

    // spatial partials: exclusive slots, direct write
    float4* os = (float4*)(Gsp_s + (size_t)cc * (B * HWc) + b * HWc + hwbase) + tid;
    float4* ot = (float4*)(Gsp_t + (size_t)cc * (B * HWc) + b * HWc + hwbase) + tid;
    *os = as;
    *ot = at;

    __syncthreads();

    // channel reduce: warp w owns channel c0+w (CCH == warps per block)
    float2 acc = make_float2(0.f, 0.f);
#pragma unroll
    for (int k = 0; k < TPB / 32; k++) {
        float2 v = stage[warp][lane + 32 * k];
        acc.x += v.x; acc.y += v.y;
    }
    F2D u2; u2.f2 = acc;
#pragma unroll
    for (int o = 16; o > 0; o >>= 1) {
        F2D v; v.d = __shfl_down_sync(0xffffffffu, u2.d, o);
        u2.f2.x += v.f2.x; u2.f2.y += v.f2.y;
    }
    if (lane == 0) {
        int idx = (b * Cc + c0 + warp) * NH + hh;
        Gcp_s[idx] = u2.f2.x;
        Gcp_t[idx] = u2.f2.y;
    }
}

__global__ void pass1_kernel(const float* __restrict__ s1, const float* __restrict__ t1,
                             const float* __restrict__ s2, const float* __restrict__ t2) {
    __shared__ float2 stage[CCH][TPB];   // 16 KB
    int bid = blockIdx.x;
    if (bid < TILES1)
        pass1_tile<C1, HW1, NC1, NH1>(s1, t1, g_d1,
            &g_Gs1p[0][0][0], &g_Gs1p[1][0][0],
            &g_Gc1p[0][0][0], &g_Gc1p[1][0][0], stage, bid);
    else
        pass1_tile<C2, HW2, NC2, NH2>(s2, t2, g_d2,
            &g_Gs2p[0][0][0], &g_Gs2p[1][0][0],
            &g_Gc2p[0][0][0], &g_Gc2p[1][0][0], stage, bid - TILES1);
}

// ---------------- softmax + lat (16 blocks; partials L2-resident) ------------
template <int Cc, int HWc, int NC, int NPART>
__device__ __forceinline__ void softmax_level(
    const float* __restrict__ Gsp_s, const float* __restrict__ Gsp_t,
    const float* __restrict__ Gcp_s, const float* __restrict__ Gcp_t,
    float* __restrict__ Ms, float* __restrict__ Mc,
    int b, float* zbuf, double* latout)
{
    const int tid = threadIdx.x;

    // ---- spatial ----
    float latp = 0.f, mx = -INFINITY;
    for (int i = tid; i < HWc; i += STPB) {
        float ss = 0.f, st = 0.f;
#pragma unroll 8
        for (int p = 0; p < NC; p++) {
            ss += Gsp_s[(size_t)p * (B * HWc) + b * HWc + i];
            st += Gsp_t[(size_t)p * (B * HWc) + b * HWc + i];
        }
        float d = ss - st;
        latp += d * d;
        float z = (ss + st) * (2.0f / (float)Cc);  // /C then /T (T=0.5)
        zbuf[i] = z;
        mx = fmaxf(mx, z);
    }
    float m = blockReduceMax(mx);
    float se = 0.f;
    for (int i = tid; i < HWc; i += STPB) {
        float e = __expf(zbuf[i] - m);
        zbuf[i] = e;
        se += e;
    }
    float S = blockReduceSum(se);
    float sc = (float)HWc / S;
    for (int i = tid; i < HWc; i += STPB) Ms[b * HWc + i] = zbuf[i] * sc;
    float lat_s = blockReduceSum(latp);

    // ---- channel ----
    float latc = 0.f, mxc = -INFINITY;
    for (int i = tid; i < Cc; i += STPB) {
        float cs = 0.f, ct = 0.f;
#pragma unroll
        for (int k = 0; k < NPART; k++) {
            cs += Gcp_s[(size_t)(b * Cc + i) * NPART + k];
            ct += Gcp_t[(size_t)(b * Cc + i) * NPART + k];
        }
        float d = cs - ct;
        latc += d * d;
        float z = (cs + ct) * (2.0f / (float)HWc);
        zbuf[i] = z;
        mxc = fmaxf(mxc, z);
    }
    float m2 = blockReduceMax(mxc);
    float sec = 0.f;
    for (int i = tid; i < Cc; i += STPB) {
        float e = __expf(zbuf[i] - m2);
        zbuf[i] = e;
        sec += e;
    }
    float Sc = blockReduceSum(sec);
    float scc = (float)Cc / Sc;
    for (int i = tid; i < Cc; i += STPB) Mc[b * Cc + i] = zbuf[i] * scc;
    float lat_c = blockReduceSum(latc);

    if (tid == 0)
        *latout = (double)lat_s / ((double)Cc * (double)Cc) +
                  (double)lat_c / ((double)HWc * (double)HWc);
}

__global__ void softmax_kernel() {
    __shared__ float zbuf[HW1];   // 16 KB
    int bid = blockIdx.x;
    if (bid == 0 && threadIdx.x == 0) g_count = 0;   // reset last-block counter
    if (bid < B)
        softmax_level<C1, HW1, NC1, NH1>(
            &g_Gs1p[0][0][0], &g_Gs1p[1][0][0],
            &g_Gc1p[0][0][0], &g_Gc1p[1][0][0],
            g_Ms1, g_Mc1, bid, zbuf, &g_latpart[bid]);
    else
        softmax_level<C2, HW2, NC2, NH2>(
            &g_Gs2p[0][0][0], &g_Gs2p[1][0][0],
            &g_Gc2p[0][0][0], &g_Gc2p[1][0][0],
            g_Ms2, g_Mc2, bid - B, zbuf, &g_latpart[bid]);
}

// ---------------- pass 2: fp16 stash read (L2), weighted SSE, fused final ----
__device__ __forceinline__ void discard_l2(const void* p) {
    unsigned long long g;
    asm("cvta.to.global.u64 %0, %1;" : "=l"(g) : "l"(p));
    asm volatile("discard.global.L2 [%0], 128;" :: "l"(g) : "memory");
}

template <int Cc, int HWc, int LOGCHW, int LOGHW, int NBLK>
__device__ __forceinline__ float pass2_range(
    const __half* __restrict__ dsrc,
    const float* __restrict__ Ms, const float* __restrict__ Mc, int bid)
{
    constexpr long long N16 = (long long)B * Cc * HWc / 8;   // uint4 = 8 halves
    constexpr long long STRIDE = (long long)NBLK * TPB;
    const uint4* d16 = (const uint4*)dsrc;
    long long gid = (long long)bid * TPB + threadIdx.x;

    float acc = 0.f;
#pragma unroll
    for (long long i = gid; i < N16; i += STRIDE) {
        uint4 v = d16[i];
        long long e = i << 3;
        int b   = (int)(e >> LOGCHW);
        int rem = (int)(e & ((1LL << LOGCHW) - 1));
        int c   = rem >> LOGHW;
        int hw  = rem & (HWc - 1);
        float mc = Mc[b * Cc + c];
        const float* msp = Ms + b * HWc + hw;
        float4 m0 = *(const float4*)msp;
        float4 m1 = *(const float4*)(msp + 4);

        float2 f0 = __half22float2(*reinterpret_cast<const __half2*>(&v.x));
        float2 f1 = __half22float2(*reinterpret_cast<const __half2*>(&v.y));
        float2 f2 = __half22float2(*reinterpret_cast<const __half2*>(&v.z));
        float2 f3 = __half22float2(*reinterpret_cast<const __half2*>(&v.w));

        float w = f0.x * f0.x * m0.x + f0.y * f0.y * m0.y
                + f1.x * f1.x * m0.z + f1.y * f1.y * m0.w
                + f2.x * f2.x * m1.x + f2.y * f2.y * m1.y
                + f3.x * f3.x * m1.z + f3.y * f3.y * m1.w;
        acc += w * mc;
    }
    return acc;
}

template <int HWc, int Cc, int NBLK>
__device__ __forceinline__ void pass2_discard(const __half* dsrc, int bid) {
    constexpr long long N16 = (long long)B * Cc * HWc / 8;
    constexpr long long STRIDE = (long long)NBLK * TPB;
    const uint4* d16 = (const uint4*)dsrc;
    long long gid = (long long)bid * TPB + threadIdx.x;
    for (long long i = gid; i < N16; i += STRIDE)
        if ((i & 7) == 0) discard_l2(&d16[i]);   // 8 uint4 = 128B line
}

__global__ void pass2_kernel(float* out, int out_size) {
    int bid = blockIdx.x;
    float acc;
    if (bid < P2B1)
        acc = pass2_range<C1, HW1, 20, 12, P2B1>(g_d1, g_Ms1, g_Mc1, bid);
    else
        acc = pass2_range<C2, HW2, 19, 10, P2B2>(g_d2, g_Ms2, g_Mc2, bid - P2B1);
    float bl = blockReduceSum(acc);   // includes __syncthreads: loads complete

    // consumed stash lines never write back to DRAM
    if (bid < P2B1) pass2_discard<HW1, C1, P2B1>(g_d1, bid);
    else            pass2_discard<HW2, C2, P2B2>(g_d2, bid - P2B1);

    __shared__ bool isLast;
    if (threadIdx.x == 0) {
        g_p2[bid] = bl;
        __threadfence();
        unsigned old = atomicAdd(&g_count, 1u);
        isLast = (old == P2TOT - 1);
    }
    __syncthreads();
    if (!isLast) return;

    // ---- fused final combine (last block) ----
    __threadfence();
    int tid = threadIdx.x;
    double a1 = 0.0, a2 = 0.0;
    for (int i = tid; i < P2B1; i += TPB) a1 += (double)g_p2[i];
    for (int i = P2B1 + tid; i < P2TOT; i += TPB) a2 += (double)g_p2[i];

    __shared__ double sh1[32], sh2[32];
    int lane = tid & 31, warp = tid >> 5;
#pragma unroll
    for (int o = 16; o > 0; o >>= 1) {
        a1 += __shfl_down_sync(0xffffffffu, a1, o);
        a2 += __shfl_down_sync(0xffffffffu, a2, o);
    }
    if (lane == 0) { sh1[warp] = a1; sh2[warp] = a2; }
    __syncthreads();
    if (tid == 0) {
        double s1 = 0.0, s2 = 0.0;
        for (int w = 0; w < TPB / 32; w++) { s1 += sh1[w]; s2 += sh2[w]; }
        double lat = 0.0;
        for (int i = 0; i < 16; i++) lat += g_latpart[i];
        double lam = sqrt(s1) + sqrt(s2);
        double att = (4e-4 * lat + 2e-2 * lam) / (double)B / 2.0;  // ATT=1, /BS, /2 levels
        out[0] = (float)(att * (double)B);
        if (out_size > 1) out[1] = (float)att;
    }
}

// ---------------- launch ------------------------------------------------------
extern "C" void kernel_launch(void* const* d_in, const int* in_sizes, int n_in,
                              void* d_out, int out_size) {
    const float* stu1 = (const float*)d_in[1];
    const float* tea1 = (const float*)d_in[2];
    const float* stu2 = (const float*)d_in[3];
    const float* tea2 = (const float*)d_in[4];
    float* out = (float*)d_out;

    pass1_kernel<<<TILES1 + TILES2, TPB>>>(stu1, tea1, stu2, tea2);
    softmax_kernel<<<16, STPB>>>();
    pass2_kernel<<<P2TOT, TPB>>>(out, out_size);
}